// round 7
// baseline (speedup 1.0000x reference)
#include <cuda_runtime.h>
#include <cstdint>
#include <math.h>

#define N_NODES 50000
#define N_EDGES 800000
#define IN_FEAT 512
#define OUT_FEAT 128

// Scratch: intermediate x = feat @ W, CSR row pointers, pre-split W fragments.
__device__ float  g_x[(size_t)N_NODES * OUT_FEAT];
__device__ int    g_row_ptr[N_NODES + 1];
// Packed pre-split B fragments: slot = kk*16 + nbg (kk 0..63, nbg 0..15),
// idx = slot*32 + lane, value = {hi(B[k][n]), hi(B[k+4][n]),
//                                lo(B[k][n]), lo(B[k+4][n])}
// with t4 = lane&3, g = lane>>2, n = nbg*8 + g, k = kk*8 + t4.   (512 KB)
__device__ float4 g_BfragHL[64 * 16 * 32];

// ---------------------------------------------------------------------------
// cp.async helpers (Ampere+ PTX, arch-portable)
// ---------------------------------------------------------------------------
__device__ __forceinline__ uint32_t smem_u32(const void* p) {
    uint32_t a;
    asm("{ .reg .u64 t; cvta.to.shared.u64 t, %1; cvt.u32.u64 %0, t; }"
        : "=r"(a) : "l"(p));
    return a;
}
__device__ __forceinline__ void cp16(uint32_t dst, const void* src, int src_bytes) {
    asm volatile("cp.async.cg.shared.global [%0], [%1], 16, %2;"
                 :: "r"(dst), "l"(src), "r"(src_bytes));
}
__device__ __forceinline__ void cp_commit() {
    asm volatile("cp.async.commit_group;" ::: "memory");
}
template <int N>
__device__ __forceinline__ void cp_wait() {
    asm volatile("cp.async.wait_group %0;" :: "n"(N) : "memory");
}

// ---------------------------------------------------------------------------
// Kernel 1: CSR row pointers via vectorized edge-boundary scatter.
// ---------------------------------------------------------------------------
__global__ void row_ptr_kernel(const int* __restrict__ rows) {
    const int t = blockIdx.x * blockDim.x + threadIdx.x;
    const int e0 = t * 4;
    if (e0 >= N_EDGES) return;
    const int4 r4 = *(const int4*)&rows[e0];
    int prev = (t == 0) ? -1 : __ldg(&rows[e0 - 1]);
    int rv[4] = {r4.x, r4.y, r4.z, r4.w};
    #pragma unroll
    for (int j = 0; j < 4; ++j) {
        for (int r = prev + 1; r <= rv[j]; ++r) g_row_ptr[r] = e0 + j;
        prev = rv[j];
    }
    if (e0 + 4 == N_EDGES) {
        for (int r = prev + 1; r <= N_NODES; ++r) g_row_ptr[r] = N_EDGES;
    }
}

// ---------------------------------------------------------------------------
// Kernel 1b: permute weight into MMA fragment order WITH tf32 hi/lo pre-split.
// ---------------------------------------------------------------------------
__device__ __forceinline__ float tf32_hi(float x) {
    return __uint_as_float(__float_as_uint(x) & 0xFFFFE000u);
}

__global__ void bfrag_kernel(const float* __restrict__ B) {
    const int idx = blockIdx.x * blockDim.x + threadIdx.x;   // 0..32767
    if (idx >= 64 * 16 * 32) return;
    const int lane = idx & 31;
    const int nbg  = (idx >> 5) & 15;
    const int kk   = idx >> 9;
    const int t4   = lane & 3;
    const int g    = lane >> 2;
    const int n    = nbg * 8 + g;
    const int k    = kk * 8 + t4;
    const float b0 = __ldg(&B[(size_t)k * OUT_FEAT + n]);
    const float b1 = __ldg(&B[(size_t)(k + 4) * OUT_FEAT + n]);
    const float h0 = tf32_hi(b0), h1 = tf32_hi(b1);
    g_BfragHL[idx] = make_float4(h0, h1, b0 - h0, b1 - h1);
}

// ---------------------------------------------------------------------------
// Kernel 2: 3xTF32 GEMM via mma.sync, cp.async pipelined, pre-split B.
//   g_x[M,128] = feat[M,512] @ W[512,128]
// CTA tile 64(M) x 128(N), 256 threads = 8 warps (2m x 4n), warp tile 32x32.
// A raw fp32 in SMEM (stride 36, conflict-free), hi/lo split in registers.
// B pre-split packed fragments in SMEM: one LDS.128 per nb, zero inner-loop
// ALU. hh + hl + lh accumulated in fp32 (~2^-21 rel error, same op order as
// previous rounds -> identical rel_err).
// ---------------------------------------------------------------------------
#define BM 64
#define KC 32
#define NCHUNK (IN_FEAT / KC)     // 16
#define A_STRIDE 36               // floats per A smem row (32 + 4 pad)
#define A_BUF_B (BM * A_STRIDE * 4)       // 9216 bytes per A buffer
#define B_BUF_B (64 * 32 * 16)            // 32768 bytes per B buffer (64 slots)
#define GEMM_SMEM (2 * A_BUF_B + 2 * B_BUF_B)   // 83968 bytes

#define MMA_TF32(cc, aa, b0, b1)                                               \
    asm volatile(                                                              \
        "mma.sync.aligned.m16n8k8.row.col.f32.tf32.tf32.f32 "                  \
        "{%0,%1,%2,%3}, {%4,%5,%6,%7}, {%8,%9}, {%0,%1,%2,%3};"                \
        : "+f"((cc)[0]), "+f"((cc)[1]), "+f"((cc)[2]), "+f"((cc)[3])           \
        : "r"((aa)[0]), "r"((aa)[1]), "r"((aa)[2]), "r"((aa)[3]),              \
          "r"(b0), "r"(b1))

__global__ __launch_bounds__(256, 2) void gemm_mma_kernel(
    const float* __restrict__ A)   // feat [N_NODES, 512]
{
    extern __shared__ char smem[];
    float* sA[2] = { (float*)smem, (float*)(smem + A_BUF_B) };
    char*  sB[2] = { smem + 2 * A_BUF_B, smem + 2 * A_BUF_B + B_BUF_B };
    const uint32_t sA_u[2] = { smem_u32(sA[0]), smem_u32(sA[1]) };
    const uint32_t sB_u[2] = { smem_u32(sB[0]), smem_u32(sB[1]) };

    const int tid  = threadIdx.x;
    const int wid  = tid >> 5;
    const int lane = tid & 31;
    const int g    = lane >> 2;    // 0..7
    const int t4   = lane & 3;     // 0..3
    const int wm   = wid >> 2;     // warp m index 0..1
    const int wn   = wid & 3;      // warp n index 0..3
    const int m0   = blockIdx.x * BM;

    // A fill: 64 rows x 8 float4 = 512 slots, 2 per thread.
    const int fm[2] = { (0 * 256 + tid) >> 3, (1 * 256 + tid) >> 3 };
    const int fk4 = tid & 7;

    auto stage = [&](int ch, int b) {
        const int k0 = ch * KC;
        #pragma unroll
        for (int it = 0; it < 2; ++it) {
            const int gm = m0 + fm[it];
            cp16(sA_u[b] + (fm[it] * A_STRIDE + fk4 * 4) * 4,
                 &A[(size_t)gm * IN_FEAT + k0 + fk4 * 4],
                 gm < N_NODES ? 16 : 0);
        }
        // B chunk: 64 slots x 512B = 32 KB, contiguous in g_BfragHL.
        const char* bsrc = (const char*)g_BfragHL + (size_t)ch * B_BUF_B;
        #pragma unroll
        for (int j = 0; j < 8; ++j)
            cp16(sB_u[b] + j * 4096 + tid * 16, bsrc + j * 4096 + tid * 16, 16);
        cp_commit();
    };

    float c[2][4][4];
    #pragma unroll
    for (int i = 0; i < 2; i++)
        #pragma unroll
        for (int j = 0; j < 4; j++)
            #pragma unroll
            for (int q = 0; q < 4; q++) c[i][j][q] = 0.0f;

    stage(0, 0);

    for (int ch = 0; ch < NCHUNK; ++ch) {
        const int buf = ch & 1;
        if (ch + 1 < NCHUNK) {
            stage(ch + 1, buf ^ 1);
            cp_wait<1>();
        } else {
            cp_wait<0>();
        }
        __syncthreads();

        const float* sa = sA[buf];
        // warp wn covers nbg in [wn*4, wn*4+4); slot = ks*16 + nbg.
        const char* bw = sB[buf] + (wn * 4) * 512 + lane * 16;

        #pragma unroll
        for (int ks = 0; ks < 4; ++ks) {
            const int kb = ks * 8;
            const char* bk = bw + ks * 16 * 512;

            // A fragments: raw LDS (conflict-free), register hi/lo split.
            uint32_t ah[2][4], al[2][4];
            #pragma unroll
            for (int mb = 0; mb < 2; ++mb) {
                const int r0 = wm * 32 + mb * 16 + g;
                const float a0 = sa[r0 * A_STRIDE + kb + t4];
                const float a1 = sa[(r0 + 8) * A_STRIDE + kb + t4];
                const float a2 = sa[r0 * A_STRIDE + kb + t4 + 4];
                const float a3 = sa[(r0 + 8) * A_STRIDE + kb + t4 + 4];
                const float h0 = tf32_hi(a0), h1 = tf32_hi(a1);
                const float h2 = tf32_hi(a2), h3 = tf32_hi(a3);
                ah[mb][0] = __float_as_uint(h0); al[mb][0] = __float_as_uint(a0 - h0);
                ah[mb][1] = __float_as_uint(h1); al[mb][1] = __float_as_uint(a1 - h1);
                ah[mb][2] = __float_as_uint(h2); al[mb][2] = __float_as_uint(a2 - h2);
                ah[mb][3] = __float_as_uint(h3); al[mb][3] = __float_as_uint(a3 - h3);
            }

            #pragma unroll
            for (int nb = 0; nb < 4; ++nb) {
                // one LDS.128: {bh0, bh1, bl0, bl1} — no inner-loop split ALU
                const float4 bf = *(const float4*)(bk + nb * 512);
                const uint32_t bh0 = __float_as_uint(bf.x);
                const uint32_t bh1 = __float_as_uint(bf.y);
                const uint32_t bl0 = __float_as_uint(bf.z);
                const uint32_t bl1 = __float_as_uint(bf.w);
                #pragma unroll
                for (int mb = 0; mb < 2; ++mb) {
                    MMA_TF32(c[mb][nb], ah[mb], bh0, bh1);   // hi*hi
                    MMA_TF32(c[mb][nb], ah[mb], bl0, bl1);   // hi*lo
                    MMA_TF32(c[mb][nb], al[mb], bh0, bh1);   // lo*hi
                }
            }
        }
        __syncthreads();
    }

    // ---- epilogue ----
    #pragma unroll
    for (int mb = 0; mb < 2; ++mb) {
        #pragma unroll
        for (int half = 0; half < 2; ++half) {
            const int row = m0 + wm * 32 + mb * 16 + g + half * 8;
            if (row < N_NODES) {
                #pragma unroll
                for (int nb = 0; nb < 4; ++nb) {
                    const int col = wn * 32 + nb * 8 + 2 * t4;
                    float2 v = make_float2(c[mb][nb][2 * half],
                                           c[mb][nb][2 * half + 1]);
                    *(float2*)&g_x[(size_t)row * OUT_FEAT + col] = v;
                }
            }
        }
    }
}

// ---------------------------------------------------------------------------
// Kernel 3: SpMM (warp per row, no atomics) + multispike epilogue.
// At the L2 gather roofline (~30 us) — leave as is.
// ---------------------------------------------------------------------------
__device__ __forceinline__ float multispike(float x) {
    return floorf(fminf(fmaxf(4.0f * x, 0.0f), 4.0f) + 0.5f) * 0.25f;
}

__global__ __launch_bounds__(256) void spmm_kernel(
    const int*   __restrict__ cols,
    const float* __restrict__ ew,
    float*       __restrict__ out)
{
    const int warp = (blockIdx.x * blockDim.x + threadIdx.x) >> 5;
    const int lane = threadIdx.x & 31;
    if (warp >= N_NODES) return;

    const int e0 = g_row_ptr[warp];
    const int e1 = g_row_ptr[warp + 1];

    float4 acc = make_float4(0.f, 0.f, 0.f, 0.f);
    const int fo = lane * 4;

    int e = e0;
    for (; e + 3 < e1; e += 4) {
        int   cc[4];
        float ww[4];
        #pragma unroll
        for (int j = 0; j < 4; ++j) { cc[j] = __ldg(&cols[e + j]); ww[j] = __ldg(&ew[e + j]); }
        #pragma unroll
        for (int j = 0; j < 4; ++j) {
            const float4 v = *(const float4*)&g_x[(size_t)cc[j] * OUT_FEAT + fo];
            acc.x = fmaf(ww[j], v.x, acc.x); acc.y = fmaf(ww[j], v.y, acc.y);
            acc.z = fmaf(ww[j], v.z, acc.z); acc.w = fmaf(ww[j], v.w, acc.w);
        }
    }
    for (; e < e1; ++e) {
        const int   c0 = __ldg(&cols[e]);
        const float w0 = __ldg(&ew[e]);
        const float4 v0 = *(const float4*)&g_x[(size_t)c0 * OUT_FEAT + fo];
        acc.x = fmaf(w0, v0.x, acc.x); acc.y = fmaf(w0, v0.y, acc.y);
        acc.z = fmaf(w0, v0.z, acc.z); acc.w = fmaf(w0, v0.w, acc.w);
    }

    acc.x = multispike(acc.x);
    acc.y = multispike(acc.y);
    acc.z = multispike(acc.z);
    acc.w = multispike(acc.w);
    *(float4*)&out[(size_t)warp * OUT_FEAT + fo] = acc;
}

// ---------------------------------------------------------------------------
extern "C" void kernel_launch(void* const* d_in, const int* in_sizes, int n_in,
                              void* d_out, int out_size) {
    const float* feat   = (const float*)d_in[0];
    const float* weight = (const float*)d_in[1];
    const int*   rows   = (const int*)d_in[2];
    const int*   cols   = (const int*)d_in[3];
    const float* ew     = (const float*)d_in[4];
    float* out = (float*)d_out;

    cudaFuncSetAttribute(gemm_mma_kernel,
                         cudaFuncAttributeMaxDynamicSharedMemorySize, GEMM_SMEM);

    row_ptr_kernel<<<(N_EDGES / 4 + 255) / 256, 256>>>(rows);
    bfrag_kernel<<<(64 * 16 * 32 + 255) / 256, 256>>>(weight);
    gemm_mma_kernel<<<(N_NODES + BM - 1) / BM, 256, GEMM_SMEM>>>(feat);
    spmm_kernel<<<(N_NODES * 32 + 255) / 256, 256>>>(cols, ew, out);
}

// round 9
// speedup vs baseline: 1.1410x; 1.1410x over previous
#include <cuda_runtime.h>
#include <cuda_bf16.h>
#include <cstdint>
#include <math.h>

#define N_NODES 50000
#define N_EDGES 800000
#define IN_FEAT 512
#define OUT_FEAT 128

// Scratch buffers.
__device__ float  g_x[(size_t)N_NODES * OUT_FEAT];
__device__ int    g_row_ptr[N_NODES + 1];
// tf32-hi B fragments (m16n8k8): slot = ks*16 + nbg (ks 0..63, nbg 0..15),
// idx = slot*32 + lane; value {rn_tf32(B[8ks+t4][n]), rn_tf32(B[8ks+t4+4][n])}
// with t4 = lane&3, g = lane>>2, n = nbg*8+g.                        (256 KB)
__device__ float2 g_Btf[64 * 16 * 32];
// bf16 B fragments (m16n8k16): slot = kk*16 + nbg (kk 0..31), idx = slot*32+lane;
// k = kk*16 + 2*t4; value {bf16x2(B[k],B[k+1]), bf16x2(B[k+8],B[k+9]),
//                          bf16x2(loB[k],loB[k+1]), bf16x2(loB[k+8],loB[k+9])}
// where loB = B - rn_tf32(B).                                        (256 KB)
__device__ uint4  g_Bbf[32 * 16 * 32];

// ---------------------------------------------------------------------------
// helpers
// ---------------------------------------------------------------------------
__device__ __forceinline__ uint32_t rn_tf32_bits(float x) {
    // round-to-nearest onto the tf32 grid (low 13 mantissa bits cleared)
    return (__float_as_uint(x) + 0x1000u) & 0xFFFFE000u;
}
__device__ __forceinline__ float rn_tf32(float x) {
    return __uint_as_float(rn_tf32_bits(x));
}
// pack {lo16 = cvt(even_k), hi16 = cvt(odd_k)} as bf16x2
__device__ __forceinline__ uint32_t pack_bf2(float even_k, float odd_k) {
    uint32_t d;
    asm("cvt.rn.bf16x2.f32 %0, %1, %2;" : "=r"(d) : "f"(odd_k), "f"(even_k));
    return d;
}

// ---------------------------------------------------------------------------
// Kernel 1: CSR row pointers via vectorized edge-boundary scatter.
// ---------------------------------------------------------------------------
__global__ void row_ptr_kernel(const int* __restrict__ rows) {
    const int t = blockIdx.x * blockDim.x + threadIdx.x;
    const int e0 = t * 4;
    if (e0 >= N_EDGES) return;
    const int4 r4 = *(const int4*)&rows[e0];
    int prev = (t == 0) ? -1 : __ldg(&rows[e0 - 1]);
    int rv[4] = {r4.x, r4.y, r4.z, r4.w};
    #pragma unroll
    for (int j = 0; j < 4; ++j) {
        for (int r = prev + 1; r <= rv[j]; ++r) g_row_ptr[r] = e0 + j;
        prev = rv[j];
    }
    if (e0 + 4 == N_EDGES) {
        for (int r = prev + 1; r <= N_NODES; ++r) g_row_ptr[r] = N_EDGES;
    }
}

// ---------------------------------------------------------------------------
// Kernel 1b: build both B fragment tables.
// ---------------------------------------------------------------------------
__global__ void bprep_kernel(const float* __restrict__ B) {
    const int idx = blockIdx.x * blockDim.x + threadIdx.x;
    if (idx < 64 * 16 * 32) {
        // tf32-hi fragments
        const int lane = idx & 31, nbg = (idx >> 5) & 15, ks = idx >> 9;
        const int t4 = lane & 3, g = lane >> 2;
        const int n = nbg * 8 + g, k = ks * 8 + t4;
        const float b0 = __ldg(&B[(size_t)k * OUT_FEAT + n]);
        const float b1 = __ldg(&B[(size_t)(k + 4) * OUT_FEAT + n]);
        g_Btf[idx] = make_float2(rn_tf32(b0), rn_tf32(b1));
    } else if (idx < 64 * 16 * 32 + 32 * 16 * 32) {
        // bf16 full + lo fragments
        const int j = idx - 64 * 16 * 32;
        const int lane = j & 31, nbg = (j >> 5) & 15, kk = j >> 9;
        const int t4 = lane & 3, g = lane >> 2;
        const int n = nbg * 8 + g, k = kk * 16 + 2 * t4;
        const float b0 = __ldg(&B[(size_t)(k + 0) * OUT_FEAT + n]);
        const float b1 = __ldg(&B[(size_t)(k + 1) * OUT_FEAT + n]);
        const float b8 = __ldg(&B[(size_t)(k + 8) * OUT_FEAT + n]);
        const float b9 = __ldg(&B[(size_t)(k + 9) * OUT_FEAT + n]);
        const float l0 = b0 - rn_tf32(b0), l1 = b1 - rn_tf32(b1);
        const float l8 = b8 - rn_tf32(b8), l9 = b9 - rn_tf32(b9);
        g_Bbf[j] = make_uint4(pack_bf2(b0, b1), pack_bf2(b8, b9),
                              pack_bf2(l0, l1), pack_bf2(l8, l9));
    }
}

// ---------------------------------------------------------------------------
// Kernel 2: GEMM  g_x[M,128] = feat[M,512] @ W[512,128]
// Scheme per k16: D += hiA*hiB (2x tf32 m16n8k8, exact tf32 products)
//               + loA*B + A*loB (2x bf16 m16n8k16 corrections; bf16 has fp32
//                 exponent range -> no subnormal flush of lo values).
// Error ~2^-18 per product, comparable to tf32x3; 64 MMAs/chunk vs 96.
// CTA 32(M) x 128(N), 128 threads = 4 n-warps, warp tile 32x32.
// A staged LDG->reg rn-split->STS each chunk (double buffered, race-free:
// STS after compute, sync before reads). B fragments direct __ldg (L2-res).
// ---------------------------------------------------------------------------
#define BM 32
#define KC 32
#define NCHUNK (IN_FEAT / KC)     // 16
#define AH_STRIDE 36              // uint32 words per A-hi row (32 + 4 pad)
#define AB_STRIDE 20              // bf16x2 words per A row (16 + 4 pad)

#define MMA_TF32(cc, aa, b0, b1)                                               \
    asm volatile(                                                              \
        "mma.sync.aligned.m16n8k8.row.col.f32.tf32.tf32.f32 "                  \
        "{%0,%1,%2,%3}, {%4,%5,%6,%7}, {%8,%9}, {%0,%1,%2,%3};"                \
        : "+f"((cc)[0]), "+f"((cc)[1]), "+f"((cc)[2]), "+f"((cc)[3])           \
        : "r"((aa)[0]), "r"((aa)[1]), "r"((aa)[2]), "r"((aa)[3]),              \
          "r"(b0), "r"(b1))

#define MMA_BF16(cc, aa, b0, b1)                                               \
    asm volatile(                                                              \
        "mma.sync.aligned.m16n8k16.row.col.f32.bf16.bf16.f32 "                 \
        "{%0,%1,%2,%3}, {%4,%5,%6,%7}, {%8,%9}, {%0,%1,%2,%3};"                \
        : "+f"((cc)[0]), "+f"((cc)[1]), "+f"((cc)[2]), "+f"((cc)[3])           \
        : "r"((aa)[0]), "r"((aa)[1]), "r"((aa)[2]), "r"((aa)[3]),              \
          "r"(b0), "r"(b1))

__global__ __launch_bounds__(128, 3) void gemm_mma_kernel(
    const float* __restrict__ A)   // feat [N_NODES, 512]
{
    __shared__ uint32_t sAhi[2][BM * AH_STRIDE];  // rn-tf32 hi (fp32 bits)
    __shared__ uint32_t sAbf[2][BM * AB_STRIDE];  // bf16x2 full A
    __shared__ uint32_t sAbl[2][BM * AB_STRIDE];  // bf16x2 lo A

    const int tid  = threadIdx.x;
    const int wn   = tid >> 5;     // warp n index 0..3
    const int lane = tid & 31;
    const int g    = lane >> 2;
    const int t4   = lane & 3;
    const int m0   = blockIdx.x * BM;

    // A fill: 32 rows x 8 float4 slots; thread -> rows {tid>>3, 16+(tid>>3)}.
    const int fm[2] = { tid >> 3, 16 + (tid >> 3) };
    const int fk4 = tid & 7;

    float4 pf[2];
    auto ldgA = [&](int ch) {
        const int k0 = ch * KC;
        #pragma unroll
        for (int it = 0; it < 2; ++it) {
            const int gm = m0 + fm[it];
            pf[it] = make_float4(0.f, 0.f, 0.f, 0.f);
            if (gm < N_NODES)
                pf[it] = *(const float4*)&A[(size_t)gm * IN_FEAT + k0 + fk4 * 4];
        }
    };
    auto stsA = [&](int b) {
        #pragma unroll
        for (int it = 0; it < 2; ++it) {
            const float4 v = pf[it];
            const uint32_t hx = rn_tf32_bits(v.x), hy = rn_tf32_bits(v.y);
            const uint32_t hz = rn_tf32_bits(v.z), hw = rn_tf32_bits(v.w);
            const float lx = v.x - __uint_as_float(hx);
            const float ly = v.y - __uint_as_float(hy);
            const float lz = v.z - __uint_as_float(hz);
            const float lw = v.w - __uint_as_float(hw);
            const int whi = fm[it] * AH_STRIDE + fk4 * 4;
            *(uint4*)&sAhi[b][whi] = make_uint4(hx, hy, hz, hw);
            const int wbf = fm[it] * AB_STRIDE + fk4 * 2;
            *(uint2*)&sAbf[b][wbf] = make_uint2(pack_bf2(v.x, v.y), pack_bf2(v.z, v.w));
            *(uint2*)&sAbl[b][wbf] = make_uint2(pack_bf2(lx, ly),   pack_bf2(lz, lw));
        }
    };

    float c[2][4][4];
    #pragma unroll
    for (int i = 0; i < 2; i++)
        #pragma unroll
        for (int j = 0; j < 4; j++)
            #pragma unroll
            for (int q = 0; q < 4; q++) c[i][j][q] = 0.0f;

    ldgA(0);
    stsA(0);

    for (int ch = 0; ch < NCHUNK; ++ch) {
        const int buf = ch & 1;
        if (ch + 1 < NCHUNK) ldgA(ch + 1);   // LDG in flight during compute
        __syncthreads();                     // stsA(ch) visible to all warps

        const uint32_t* ahp = sAhi[buf];
        const uint32_t* afp = sAbf[buf];
        const uint32_t* alp = sAbl[buf];

        #pragma unroll
        for (int ks2 = 0; ks2 < 2; ++ks2) {        // k16 blocks in chunk
            // ---- B fragments (direct from L2-resident tables) ----
            uint4 bb[4];
            float2 bt[2][4];
            #pragma unroll
            for (int nb = 0; nb < 4; ++nb) {
                const int nbg = wn * 4 + nb;
                bb[nb] = __ldg(&g_Bbf[(size_t)((ch * 2 + ks2) * 16 + nbg) * 32 + lane]);
                bt[0][nb] = __ldg(&g_Btf[(size_t)((ch * 4 + ks2 * 2 + 0) * 16 + nbg) * 32 + lane]);
                bt[1][nb] = __ldg(&g_Btf[(size_t)((ch * 4 + ks2 * 2 + 1) * 16 + nbg) * 32 + lane]);
            }

            // ---- A tf32-hi fragments (two k8 halves) ----
            uint32_t ath[2][2][4];   // [h][mb][4]
            #pragma unroll
            for (int h = 0; h < 2; ++h) {
                const int kb = ks2 * 16 + h * 8;
                #pragma unroll
                for (int mb = 0; mb < 2; ++mb) {
                    const int r0 = mb * 16 + g;
                    ath[h][mb][0] = ahp[r0 * AH_STRIDE + kb + t4];
                    ath[h][mb][1] = ahp[(r0 + 8) * AH_STRIDE + kb + t4];
                    ath[h][mb][2] = ahp[r0 * AH_STRIDE + kb + t4 + 4];
                    ath[h][mb][3] = ahp[(r0 + 8) * AH_STRIDE + kb + t4 + 4];
                }
            }
            // ---- A bf16 fragments (k16) ----
            uint32_t afl[2][4], all_[2][4];
            #pragma unroll
            for (int mb = 0; mb < 2; ++mb) {
                const int r0 = mb * 16 + g;
                const int w0 = r0 * AB_STRIDE + ks2 * 8 + t4;
                const int w8 = (r0 + 8) * AB_STRIDE + ks2 * 8 + t4;
                afl[mb][0] = afp[w0];     afl[mb][1] = afp[w8];
                afl[mb][2] = afp[w0 + 4]; afl[mb][3] = afp[w8 + 4];
                all_[mb][0] = alp[w0];     all_[mb][1] = alp[w8];
                all_[mb][2] = alp[w0 + 4]; all_[mb][3] = alp[w8 + 4];
            }

            #pragma unroll
            for (int nb = 0; nb < 4; ++nb) {
                #pragma unroll
                for (int mb = 0; mb < 2; ++mb) {
                    MMA_TF32(c[mb][nb], ath[0][mb],
                             __float_as_uint(bt[0][nb].x), __float_as_uint(bt[0][nb].y));
                    MMA_TF32(c[mb][nb], ath[1][mb],
                             __float_as_uint(bt[1][nb].x), __float_as_uint(bt[1][nb].y));
                    MMA_BF16(c[mb][nb], all_[mb], bb[nb].x, bb[nb].y);  // loA * B
                    MMA_BF16(c[mb][nb], afl[mb],  bb[nb].z, bb[nb].w);  // A * loB
                }
            }
        }

        // stage next chunk into the other buffer (all warps passed this
        // iteration's sync -> nobody still reads buf^1)
        if (ch + 1 < NCHUNK) stsA(buf ^ 1);
    }

    // ---- epilogue ----
    #pragma unroll
    for (int mb = 0; mb < 2; ++mb) {
        #pragma unroll
        for (int half = 0; half < 2; ++half) {
            const int row = m0 + mb * 16 + g + half * 8;
            if (row < N_NODES) {
                #pragma unroll
                for (int nb = 0; nb < 4; ++nb) {
                    const int col = wn * 32 + nb * 8 + 2 * t4;
                    float2 v = make_float2(c[mb][nb][2 * half],
                                           c[mb][nb][2 * half + 1]);
                    *(float2*)&g_x[(size_t)row * OUT_FEAT + col] = v;
                }
            }
        }
    }
}

// ---------------------------------------------------------------------------
// Kernel 3: SpMM (warp per row, no atomics) + multispike epilogue.
// At the L2 gather roofline (~30 us) — unchanged.
// ---------------------------------------------------------------------------
__device__ __forceinline__ float multispike(float x) {
    return floorf(fminf(fmaxf(4.0f * x, 0.0f), 4.0f) + 0.5f) * 0.25f;
}

__global__ __launch_bounds__(256) void spmm_kernel(
    const int*   __restrict__ cols,
    const float* __restrict__ ew,
    float*       __restrict__ out)
{
    const int warp = (blockIdx.x * blockDim.x + threadIdx.x) >> 5;
    const int lane = threadIdx.x & 31;
    if (warp >= N_NODES) return;

    const int e0 = g_row_ptr[warp];
    const int e1 = g_row_ptr[warp + 1];

    float4 acc = make_float4(0.f, 0.f, 0.f, 0.f);
    const int fo = lane * 4;

    int e = e0;
    for (; e + 3 < e1; e += 4) {
        int   cc[4];
        float ww[4];
        #pragma unroll
        for (int j = 0; j < 4; ++j) { cc[j] = __ldg(&cols[e + j]); ww[j] = __ldg(&ew[e + j]); }
        #pragma unroll
        for (int j = 0; j < 4; ++j) {
            const float4 v = *(const float4*)&g_x[(size_t)cc[j] * OUT_FEAT + fo];
            acc.x = fmaf(ww[j], v.x, acc.x); acc.y = fmaf(ww[j], v.y, acc.y);
            acc.z = fmaf(ww[j], v.z, acc.z); acc.w = fmaf(ww[j], v.w, acc.w);
        }
    }
    for (; e < e1; ++e) {
        const int   c0 = __ldg(&cols[e]);
        const float w0 = __ldg(&ew[e]);
        const float4 v0 = *(const float4*)&g_x[(size_t)c0 * OUT_FEAT + fo];
        acc.x = fmaf(w0, v0.x, acc.x); acc.y = fmaf(w0, v0.y, acc.y);
        acc.z = fmaf(w0, v0.z, acc.z); acc.w = fmaf(w0, v0.w, acc.w);
    }

    acc.x = multispike(acc.x);
    acc.y = multispike(acc.y);
    acc.z = multispike(acc.z);
    acc.w = multispike(acc.w);
    *(float4*)&out[(size_t)warp * OUT_FEAT + fo] = acc;
}

// ---------------------------------------------------------------------------
extern "C" void kernel_launch(void* const* d_in, const int* in_sizes, int n_in,
                              void* d_out, int out_size) {
    const float* feat   = (const float*)d_in[0];
    const float* weight = (const float*)d_in[1];
    const int*   rows   = (const int*)d_in[2];
    const int*   cols   = (const int*)d_in[3];
    const float* ew     = (const float*)d_in[4];
    float* out = (float*)d_out;

    row_ptr_kernel<<<(N_EDGES / 4 + 255) / 256, 256>>>(rows);
    bprep_kernel<<<(64 * 16 * 32 + 32 * 16 * 32 + 255) / 256, 256>>>(weight);
    gemm_mma_kernel<<<(N_NODES + BM - 1) / BM, 128>>>(feat);
    spmm_kernel<<<(N_NODES * 32 + 255) / 256, 256>>>(cols, ew, out);
}

// round 10
// speedup vs baseline: 1.2088x; 1.0594x over previous
#include <cuda_runtime.h>
#include <cuda_bf16.h>
#include <cstdint>
#include <math.h>

#define N_NODES 50000
#define N_EDGES 800000
#define IN_FEAT 512
#define OUT_FEAT 128

// Scratch buffers.
__device__ float  g_x[(size_t)N_NODES * OUT_FEAT];
__device__ int    g_row_ptr[N_NODES + 1];
// tf32-hi B fragments, packed per k16 step: slot = s*16 + nbg (s 0..31),
// idx = slot*32 + lane; value {rn(B[k]), rn(B[k+4]), rn(B[k+8]), rn(B[k+12])}
// at column n = nbg*8 + (lane>>2), k = s*16 + (lane&3).              (256 KB)
__device__ float4 g_Btf[32 * 16 * 32];
// bf16 B fragments (m16n8k16): slot = s*16 + nbg, idx = slot*32 + lane;
// k = s*16 + 2*t4; value {bf16x2(B[k],B[k+1]), bf16x2(B[k+8],B[k+9]),
//                         bf16x2(loB[k],loB[k+1]), bf16x2(loB[k+8],loB[k+9])}
// where loB = B - rn_tf32(B).                                        (256 KB)
__device__ uint4  g_Bbf[32 * 16 * 32];

// ---------------------------------------------------------------------------
// helpers
// ---------------------------------------------------------------------------
__device__ __forceinline__ uint32_t rn_tf32_bits(float x) {
    return (__float_as_uint(x) + 0x1000u) & 0xFFFFE000u;
}
__device__ __forceinline__ float rn_tf32(float x) {
    return __uint_as_float(rn_tf32_bits(x));
}
__device__ __forceinline__ uint32_t pack_bf2(float even_k, float odd_k) {
    uint32_t d;
    asm("cvt.rn.bf16x2.f32 %0, %1, %2;" : "=r"(d) : "f"(odd_k), "f"(even_k));
    return d;
}

// ---------------------------------------------------------------------------
// Kernel 1: CSR row pointers via vectorized edge-boundary scatter.
// ---------------------------------------------------------------------------
__global__ void row_ptr_kernel(const int* __restrict__ rows) {
    const int t = blockIdx.x * blockDim.x + threadIdx.x;
    const int e0 = t * 4;
    if (e0 >= N_EDGES) return;
    const int4 r4 = *(const int4*)&rows[e0];
    int prev = (t == 0) ? -1 : __ldg(&rows[e0 - 1]);
    int rv[4] = {r4.x, r4.y, r4.z, r4.w};
    #pragma unroll
    for (int j = 0; j < 4; ++j) {
        for (int r = prev + 1; r <= rv[j]; ++r) g_row_ptr[r] = e0 + j;
        prev = rv[j];
    }
    if (e0 + 4 == N_EDGES) {
        for (int r = prev + 1; r <= N_NODES; ++r) g_row_ptr[r] = N_EDGES;
    }
}

// ---------------------------------------------------------------------------
// Kernel 1b: build both B fragment tables.
// ---------------------------------------------------------------------------
__global__ void bprep_kernel(const float* __restrict__ B) {
    const int idx = blockIdx.x * blockDim.x + threadIdx.x;
    if (idx >= 32 * 16 * 32) return;
    const int lane = idx & 31, nbg = (idx >> 5) & 15, s = idx >> 9;
    const int t4 = lane & 3, g = lane >> 2;
    const int n = nbg * 8 + g;
    {   // tf32-hi packed (k = s*16 + t4 + {0,4,8,12})
        const int k = s * 16 + t4;
        g_Btf[idx] = make_float4(
            rn_tf32(__ldg(&B[(size_t)(k + 0)  * OUT_FEAT + n])),
            rn_tf32(__ldg(&B[(size_t)(k + 4)  * OUT_FEAT + n])),
            rn_tf32(__ldg(&B[(size_t)(k + 8)  * OUT_FEAT + n])),
            rn_tf32(__ldg(&B[(size_t)(k + 12) * OUT_FEAT + n])));
    }
    {   // bf16 full + lo (k = s*16 + 2*t4 + {0,1,8,9})
        const int k = s * 16 + 2 * t4;
        const float b0 = __ldg(&B[(size_t)(k + 0) * OUT_FEAT + n]);
        const float b1 = __ldg(&B[(size_t)(k + 1) * OUT_FEAT + n]);
        const float b8 = __ldg(&B[(size_t)(k + 8) * OUT_FEAT + n]);
        const float b9 = __ldg(&B[(size_t)(k + 9) * OUT_FEAT + n]);
        const float l0 = b0 - rn_tf32(b0), l1 = b1 - rn_tf32(b1);
        const float l8 = b8 - rn_tf32(b8), l9 = b9 - rn_tf32(b9);
        g_Bbf[idx] = make_uint4(pack_bf2(b0, b1), pack_bf2(b8, b9),
                                pack_bf2(l0, l1), pack_bf2(l8, l9));
    }
}

// ---------------------------------------------------------------------------
// Kernel 2: GEMM  g_x[M,128] = feat[M,512] @ W[512,128]
// Per k16 step: D += hiA*hiB (2x tf32 m16n8k8) + loA*B + A*loB (2x bf16
// m16n8k16). B fragments register-prefetched ONE STEP AHEAD (double-banked
// by step parity) so the ~250cyc L2 latency is covered by the previous
// step's MMAs. CTA 32(M) x 128(N), 128 threads, warp tile 32x32.
// ---------------------------------------------------------------------------
#define BM 32
#define KC 32
#define NCHUNK (IN_FEAT / KC)     // 16
#define NSTEP 32                  // k16 steps total
#define AH_STRIDE 36
#define AB_STRIDE 20

#define MMA_TF32(cc, aa, b0, b1)                                               \
    asm volatile(                                                              \
        "mma.sync.aligned.m16n8k8.row.col.f32.tf32.tf32.f32 "                  \
        "{%0,%1,%2,%3}, {%4,%5,%6,%7}, {%8,%9}, {%0,%1,%2,%3};"                \
        : "+f"((cc)[0]), "+f"((cc)[1]), "+f"((cc)[2]), "+f"((cc)[3])           \
        : "r"((aa)[0]), "r"((aa)[1]), "r"((aa)[2]), "r"((aa)[3]),              \
          "r"(b0), "r"(b1))

#define MMA_BF16(cc, aa, b0, b1)                                               \
    asm volatile(                                                              \
        "mma.sync.aligned.m16n8k16.row.col.f32.bf16.bf16.f32 "                 \
        "{%0,%1,%2,%3}, {%4,%5,%6,%7}, {%8,%9}, {%0,%1,%2,%3};"                \
        : "+f"((cc)[0]), "+f"((cc)[1]), "+f"((cc)[2]), "+f"((cc)[3])           \
        : "r"((aa)[0]), "r"((aa)[1]), "r"((aa)[2]), "r"((aa)[3]),              \
          "r"(b0), "r"(b1))

__global__ __launch_bounds__(128, 3) void gemm_mma_kernel(
    const float* __restrict__ A)   // feat [N_NODES, 512]
{
    __shared__ uint32_t sAhi[2][BM * AH_STRIDE];
    __shared__ uint32_t sAbf[2][BM * AB_STRIDE];
    __shared__ uint32_t sAbl[2][BM * AB_STRIDE];

    const int tid  = threadIdx.x;
    const int wn   = tid >> 5;
    const int lane = tid & 31;
    const int g    = lane >> 2;
    const int t4   = lane & 3;
    const int m0   = blockIdx.x * BM;

    const int fm[2] = { tid >> 3, 16 + (tid >> 3) };
    const int fk4 = tid & 7;

    float4 pf[2];
    auto ldgA = [&](int ch) {
        const int k0 = ch * KC;
        #pragma unroll
        for (int it = 0; it < 2; ++it) {
            const int gm = m0 + fm[it];
            pf[it] = make_float4(0.f, 0.f, 0.f, 0.f);
            if (gm < N_NODES)
                pf[it] = *(const float4*)&A[(size_t)gm * IN_FEAT + k0 + fk4 * 4];
        }
    };
    auto stsA = [&](int b) {
        #pragma unroll
        for (int it = 0; it < 2; ++it) {
            const float4 v = pf[it];
            const uint32_t hx = rn_tf32_bits(v.x), hy = rn_tf32_bits(v.y);
            const uint32_t hz = rn_tf32_bits(v.z), hw = rn_tf32_bits(v.w);
            const float lx = v.x - __uint_as_float(hx);
            const float ly = v.y - __uint_as_float(hy);
            const float lz = v.z - __uint_as_float(hz);
            const float lw = v.w - __uint_as_float(hw);
            const int whi = fm[it] * AH_STRIDE + fk4 * 4;
            *(uint4*)&sAhi[b][whi] = make_uint4(hx, hy, hz, hw);
            const int wbf = fm[it] * AB_STRIDE + fk4 * 2;
            *(uint2*)&sAbf[b][wbf] = make_uint2(pack_bf2(v.x, v.y), pack_bf2(v.z, v.w));
            *(uint2*)&sAbl[b][wbf] = make_uint2(pack_bf2(lx, ly),   pack_bf2(lz, lw));
        }
    };

    // B register banks, indexed by step parity.
    uint4  bb[2][4];
    float4 bt[2][4];
    auto ldB = [&](int s, int p) {
        #pragma unroll
        for (int nb = 0; nb < 4; ++nb) {
            const size_t slot = (size_t)(s * 16 + wn * 4 + nb) * 32 + lane;
            bb[p][nb] = __ldg(&g_Bbf[slot]);
            bt[p][nb] = __ldg(&g_Btf[slot]);
        }
    };

    float c[2][4][4];
    #pragma unroll
    for (int i = 0; i < 2; i++)
        #pragma unroll
        for (int j = 0; j < 4; j++)
            #pragma unroll
            for (int q = 0; q < 4; q++) c[i][j][q] = 0.0f;

    ldB(0, 0);
    ldgA(0);
    stsA(0);

    for (int ch = 0; ch < NCHUNK; ++ch) {
        const int buf = ch & 1;
        if (ch + 1 < NCHUNK) ldgA(ch + 1);
        __syncthreads();

        const uint32_t* ahp = sAhi[buf];
        const uint32_t* afp = sAbf[buf];
        const uint32_t* alp = sAbl[buf];

        #pragma unroll
        for (int ks2 = 0; ks2 < 2; ++ks2) {
            const int s = ch * 2 + ks2;
            const int p = s & 1;
            if (s + 1 < NSTEP) ldB(s + 1, p ^ 1);   // prefetch next step's B

            #pragma unroll
            for (int mb = 0; mb < 2; ++mb) {
                // A fragments for this mb only (16 regs live)
                const int r0 = mb * 16 + g;
                uint32_t ath[2][4];
                #pragma unroll
                for (int h = 0; h < 2; ++h) {
                    const int kb = ks2 * 16 + h * 8;
                    ath[h][0] = ahp[r0 * AH_STRIDE + kb + t4];
                    ath[h][1] = ahp[(r0 + 8) * AH_STRIDE + kb + t4];
                    ath[h][2] = ahp[r0 * AH_STRIDE + kb + t4 + 4];
                    ath[h][3] = ahp[(r0 + 8) * AH_STRIDE + kb + t4 + 4];
                }
                uint32_t afl[4], all_[4];
                {
                    const int w0 = r0 * AB_STRIDE + ks2 * 8 + t4;
                    const int w8 = (r0 + 8) * AB_STRIDE + ks2 * 8 + t4;
                    afl[0] = afp[w0];     afl[1] = afp[w8];
                    afl[2] = afp[w0 + 4]; afl[3] = afp[w8 + 4];
                    all_[0] = alp[w0];     all_[1] = alp[w8];
                    all_[2] = alp[w0 + 4]; all_[3] = alp[w8 + 4];
                }

                #pragma unroll
                for (int nb = 0; nb < 4; ++nb) {
                    MMA_TF32(c[mb][nb], ath[0],
                             __float_as_uint(bt[p][nb].x), __float_as_uint(bt[p][nb].y));
                    MMA_TF32(c[mb][nb], ath[1],
                             __float_as_uint(bt[p][nb].z), __float_as_uint(bt[p][nb].w));
                    MMA_BF16(c[mb][nb], all_, bb[p][nb].x, bb[p][nb].y);  // loA * B
                    MMA_BF16(c[mb][nb], afl,  bb[p][nb].z, bb[p][nb].w);  // A * loB
                }
            }
        }

        if (ch + 1 < NCHUNK) stsA(buf ^ 1);
    }

    // ---- epilogue ----
    #pragma unroll
    for (int mb = 0; mb < 2; ++mb) {
        #pragma unroll
        for (int half = 0; half < 2; ++half) {
            const int row = m0 + mb * 16 + g + half * 8;
            if (row < N_NODES) {
                #pragma unroll
                for (int nb = 0; nb < 4; ++nb) {
                    const int col = wn * 32 + nb * 8 + 2 * t4;
                    float2 v = make_float2(c[mb][nb][2 * half],
                                           c[mb][nb][2 * half + 1]);
                    *(float2*)&g_x[(size_t)row * OUT_FEAT + col] = v;
                }
            }
        }
    }
}

// ---------------------------------------------------------------------------
// Kernel 3: SpMM (warp per row, no atomics) + multispike epilogue.
// At the L2 gather roofline (~30 us) — unchanged.
// ---------------------------------------------------------------------------
__device__ __forceinline__ float multispike(float x) {
    return floorf(fminf(fmaxf(4.0f * x, 0.0f), 4.0f) + 0.5f) * 0.25f;
}

__global__ __launch_bounds__(256) void spmm_kernel(
    const int*   __restrict__ cols,
    const float* __restrict__ ew,
    float*       __restrict__ out)
{
    const int warp = (blockIdx.x * blockDim.x + threadIdx.x) >> 5;
    const int lane = threadIdx.x & 31;
    if (warp >= N_NODES) return;

    const int e0 = g_row_ptr[warp];
    const int e1 = g_row_ptr[warp + 1];

    float4 acc = make_float4(0.f, 0.f, 0.f, 0.f);
    const int fo = lane * 4;

    int e = e0;
    for (; e + 3 < e1; e += 4) {
        int   cc[4];
        float ww[4];
        #pragma unroll
        for (int j = 0; j < 4; ++j) { cc[j] = __ldg(&cols[e + j]); ww[j] = __ldg(&ew[e + j]); }
        #pragma unroll
        for (int j = 0; j < 4; ++j) {
            const float4 v = *(const float4*)&g_x[(size_t)cc[j] * OUT_FEAT + fo];
            acc.x = fmaf(ww[j], v.x, acc.x); acc.y = fmaf(ww[j], v.y, acc.y);
            acc.z = fmaf(ww[j], v.z, acc.z); acc.w = fmaf(ww[j], v.w, acc.w);
        }
    }
    for (; e < e1; ++e) {
        const int   c0 = __ldg(&cols[e]);
        const float w0 = __ldg(&ew[e]);
        const float4 v0 = *(const float4*)&g_x[(size_t)c0 * OUT_FEAT + fo];
        acc.x = fmaf(w0, v0.x, acc.x); acc.y = fmaf(w0, v0.y, acc.y);
        acc.z = fmaf(w0, v0.z, acc.z); acc.w = fmaf(w0, v0.w, acc.w);
    }

    acc.x = multispike(acc.x);
    acc.y = multispike(acc.y);
    acc.z = multispike(acc.z);
    acc.w = multispike(acc.w);
    *(float4*)&out[(size_t)warp * OUT_FEAT + fo] = acc;
}

// ---------------------------------------------------------------------------
extern "C" void kernel_launch(void* const* d_in, const int* in_sizes, int n_in,
                              void* d_out, int out_size) {
    const float* feat   = (const float*)d_in[0];
    const float* weight = (const float*)d_in[1];
    const int*   rows   = (const int*)d_in[2];
    const int*   cols   = (const int*)d_in[3];
    const float* ew     = (const float*)d_in[4];
    float* out = (float*)d_out;

    row_ptr_kernel<<<(N_EDGES / 4 + 255) / 256, 256>>>(rows);
    bprep_kernel<<<(32 * 16 * 32 + 255) / 256, 256>>>(weight);
    gemm_mma_kernel<<<(N_NODES + BM - 1) / BM, 128>>>(feat);
    spmm_kernel<<<(N_NODES * 32 + 255) / 256, 256>>>(cols, ew, out);
}

// round 11
// speedup vs baseline: 1.3228x; 1.0943x over previous
#include <cuda_runtime.h>
#include <cuda_fp16.h>
#include <cstdint>
#include <math.h>

#define N_NODES 50000
#define N_EDGES 800000
#define IN_FEAT 512
#define OUT_FEAT 128

#define LO_SCALE 2048.0f
#define LO_INV   (1.0f / 2048.0f)

// Scratch buffers.
__device__ float  g_x[(size_t)N_NODES * OUT_FEAT];
__device__ int    g_row_ptr[N_NODES + 1];
// fp16 B fragments (m16n8k16): slot = s*16 + nbg (s 0..31, nbg 0..15),
// idx = slot*32 + lane; n = nbg*8 + (lane>>2), k = s*16 + 2*(lane&3);
// value {f16x2(hiB[k],hiB[k+1]), f16x2(hiB[k+8],hiB[k+9]),
//        f16x2(loB_s[k],loB_s[k+1]), f16x2(loB_s[k+8],loB_s[k+9])}
// where hiB = fp16(B), loB_s = fp16(2048*(B - hiB)).                 (256 KB)
__device__ uint4 g_Bf16[32 * 16 * 32];

// ---------------------------------------------------------------------------
// helpers
// ---------------------------------------------------------------------------
__device__ __forceinline__ uint32_t h2_bits(__half2 h) { return *(uint32_t*)&h; }

// ---------------------------------------------------------------------------
// Kernel 1: CSR row pointers via vectorized edge-boundary scatter.
// ---------------------------------------------------------------------------
__global__ void row_ptr_kernel(const int* __restrict__ rows) {
    const int t = blockIdx.x * blockDim.x + threadIdx.x;
    const int e0 = t * 4;
    if (e0 >= N_EDGES) return;
    const int4 r4 = *(const int4*)&rows[e0];
    int prev = (t == 0) ? -1 : __ldg(&rows[e0 - 1]);
    int rv[4] = {r4.x, r4.y, r4.z, r4.w};
    #pragma unroll
    for (int j = 0; j < 4; ++j) {
        for (int r = prev + 1; r <= rv[j]; ++r) g_row_ptr[r] = e0 + j;
        prev = rv[j];
    }
    if (e0 + 4 == N_EDGES) {
        for (int r = prev + 1; r <= N_NODES; ++r) g_row_ptr[r] = N_EDGES;
    }
}

// ---------------------------------------------------------------------------
// Kernel 1b: build fp16 hi / scaled-lo B fragment table.
// ---------------------------------------------------------------------------
__global__ void bprep_kernel(const float* __restrict__ B) {
    const int idx = blockIdx.x * blockDim.x + threadIdx.x;
    if (idx >= 32 * 16 * 32) return;
    const int lane = idx & 31, nbg = (idx >> 5) & 15, s = idx >> 9;
    const int t4 = lane & 3, g = lane >> 2;
    const int n = nbg * 8 + g;
    const int k = s * 16 + 2 * t4;

    const float b0 = __ldg(&B[(size_t)(k + 0) * OUT_FEAT + n]);
    const float b1 = __ldg(&B[(size_t)(k + 1) * OUT_FEAT + n]);
    const float b8 = __ldg(&B[(size_t)(k + 8) * OUT_FEAT + n]);
    const float b9 = __ldg(&B[(size_t)(k + 9) * OUT_FEAT + n]);

    __half2 h01 = __floats2half2_rn(b0, b1);
    __half2 h89 = __floats2half2_rn(b8, b9);
    float2 f01 = __half22float2(h01);
    float2 f89 = __half22float2(h89);
    __half2 l01 = __floats2half2_rn((b0 - f01.x) * LO_SCALE, (b1 - f01.y) * LO_SCALE);
    __half2 l89 = __floats2half2_rn((b8 - f89.x) * LO_SCALE, (b9 - f89.y) * LO_SCALE);
    g_Bf16[idx] = make_uint4(h2_bits(h01), h2_bits(h89), h2_bits(l01), h2_bits(l89));
}

// ---------------------------------------------------------------------------
// Kernel 2: GEMM  g_x[M,128] = feat[M,512] @ W[512,128]
// fp16 "2-accumulator" split: x = hi + lo_s/2048 with hi = fp16(x),
// lo_s = fp16(2048*(x-hi)) (scaling keeps lo in fp16 NORMAL range — this is
// what R8 lacked). Per k16 step, 3 fp16 m16n8k16 MMAs:
//   c  += hiA*hiB
//   c2 += loA_s*hiB + hiA*loB_s          (c_final = c + c2/2048)
// Omitted lo*lo and representation error ~2^-22 — same class as tf32x3.
// CTA 32(M) x 128(N), 128 threads, warp tile 32x32. A staged via reg-split
// -> SMEM (double buffered); B fragments register-prefetched one step ahead.
// ---------------------------------------------------------------------------
#define BM 32
#define KC 32
#define NCHUNK (IN_FEAT / KC)     // 16
#define NSTEP 32
#define AB_STRIDE 20              // f16x2 words per A row (16 + 4 pad)

#define MMA_F16(cc, aa, b0, b1)                                                \
    asm volatile(                                                              \
        "mma.sync.aligned.m16n8k16.row.col.f32.f16.f16.f32 "                   \
        "{%0,%1,%2,%3}, {%4,%5,%6,%7}, {%8,%9}, {%0,%1,%2,%3};"                \
        : "+f"((cc)[0]), "+f"((cc)[1]), "+f"((cc)[2]), "+f"((cc)[3])           \
        : "r"((aa)[0]), "r"((aa)[1]), "r"((aa)[2]), "r"((aa)[3]),              \
          "r"(b0), "r"(b1))

__global__ __launch_bounds__(128, 3) void gemm_mma_kernel(
    const float* __restrict__ A)   // feat [N_NODES, 512]
{
    __shared__ uint32_t sAh[2][BM * AB_STRIDE];   // fp16x2 hi
    __shared__ uint32_t sAl[2][BM * AB_STRIDE];   // fp16x2 scaled lo

    const int tid  = threadIdx.x;
    const int wn   = tid >> 5;
    const int lane = tid & 31;
    const int g    = lane >> 2;
    const int t4   = lane & 3;
    const int m0   = blockIdx.x * BM;

    const int fm[2] = { tid >> 3, 16 + (tid >> 3) };
    const int fk4 = tid & 7;

    float4 pf[2];
    auto ldgA = [&](int ch) {
        const int k0 = ch * KC;
        #pragma unroll
        for (int it = 0; it < 2; ++it) {
            const int gm = m0 + fm[it];
            pf[it] = make_float4(0.f, 0.f, 0.f, 0.f);
            if (gm < N_NODES)
                pf[it] = *(const float4*)&A[(size_t)gm * IN_FEAT + k0 + fk4 * 4];
        }
    };
    auto stsA = [&](int b) {
        #pragma unroll
        for (int it = 0; it < 2; ++it) {
            const float4 v = pf[it];
            __half2 h01 = __floats2half2_rn(v.x, v.y);
            __half2 h23 = __floats2half2_rn(v.z, v.w);
            float2 f01 = __half22float2(h01);
            float2 f23 = __half22float2(h23);
            __half2 l01 = __floats2half2_rn((v.x - f01.x) * LO_SCALE,
                                            (v.y - f01.y) * LO_SCALE);
            __half2 l23 = __floats2half2_rn((v.z - f23.x) * LO_SCALE,
                                            (v.w - f23.y) * LO_SCALE);
            const int w = fm[it] * AB_STRIDE + fk4 * 2;
            *(uint2*)&sAh[b][w] = make_uint2(h2_bits(h01), h2_bits(h23));
            *(uint2*)&sAl[b][w] = make_uint2(h2_bits(l01), h2_bits(l23));
        }
    };

    // B register banks by step parity.
    uint4 bf[2][4];
    auto ldB = [&](int s, int p) {
        #pragma unroll
        for (int nb = 0; nb < 4; ++nb)
            bf[p][nb] = __ldg(&g_Bf16[(size_t)(s * 16 + wn * 4 + nb) * 32 + lane]);
    };

    float c[2][4][4], c2[2][4][4];
    #pragma unroll
    for (int i = 0; i < 2; i++)
        #pragma unroll
        for (int j = 0; j < 4; j++)
            #pragma unroll
            for (int q = 0; q < 4; q++) { c[i][j][q] = 0.0f; c2[i][j][q] = 0.0f; }

    ldB(0, 0);
    ldgA(0);
    stsA(0);

    for (int ch = 0; ch < NCHUNK; ++ch) {
        const int buf = ch & 1;
        if (ch + 1 < NCHUNK) ldgA(ch + 1);
        __syncthreads();

        const uint32_t* ahp = sAh[buf];
        const uint32_t* alp = sAl[buf];

        #pragma unroll
        for (int ks2 = 0; ks2 < 2; ++ks2) {
            const int s = ch * 2 + ks2;
            const int p = s & 1;
            if (s + 1 < NSTEP) ldB(s + 1, p ^ 1);   // prefetch next step's B

            #pragma unroll
            for (int mb = 0; mb < 2; ++mb) {
                const int r0 = mb * 16 + g;
                const int w0 = r0 * AB_STRIDE + ks2 * 8 + t4;
                const int w8 = (r0 + 8) * AB_STRIDE + ks2 * 8 + t4;
                uint32_t ah[4], al[4];
                ah[0] = ahp[w0];     ah[1] = ahp[w8];
                ah[2] = ahp[w0 + 4]; ah[3] = ahp[w8 + 4];
                al[0] = alp[w0];     al[1] = alp[w8];
                al[2] = alp[w0 + 4]; al[3] = alp[w8 + 4];

                #pragma unroll
                for (int nb = 0; nb < 4; ++nb) {
                    MMA_F16(c [mb][nb], ah, bf[p][nb].x, bf[p][nb].y);  // hi*hi
                    MMA_F16(c2[mb][nb], al, bf[p][nb].x, bf[p][nb].y);  // loA_s*hiB
                    MMA_F16(c2[mb][nb], ah, bf[p][nb].z, bf[p][nb].w);  // hiA*loB_s
                }
            }
        }

        if (ch + 1 < NCHUNK) stsA(buf ^ 1);
    }

    // ---- epilogue: combine main + scaled corrections ----
    #pragma unroll
    for (int mb = 0; mb < 2; ++mb) {
        #pragma unroll
        for (int half = 0; half < 2; ++half) {
            const int row = m0 + mb * 16 + g + half * 8;
            if (row < N_NODES) {
                #pragma unroll
                for (int nb = 0; nb < 4; ++nb) {
                    const int col = wn * 32 + nb * 8 + 2 * t4;
                    float2 v = make_float2(
                        fmaf(c2[mb][nb][2 * half],     LO_INV, c[mb][nb][2 * half]),
                        fmaf(c2[mb][nb][2 * half + 1], LO_INV, c[mb][nb][2 * half + 1]));
                    *(float2*)&g_x[(size_t)row * OUT_FEAT + col] = v;
                }
            }
        }
    }
}

// ---------------------------------------------------------------------------
// Kernel 3: SpMM (warp per row, no atomics) + multispike epilogue.
// At the L2 gather roofline (~30 us) — unchanged.
// ---------------------------------------------------------------------------
__device__ __forceinline__ float multispike(float x) {
    return floorf(fminf(fmaxf(4.0f * x, 0.0f), 4.0f) + 0.5f) * 0.25f;
}

__global__ __launch_bounds__(256) void spmm_kernel(
    const int*   __restrict__ cols,
    const float* __restrict__ ew,
    float*       __restrict__ out)
{
    const int warp = (blockIdx.x * blockDim.x + threadIdx.x) >> 5;
    const int lane = threadIdx.x & 31;
    if (warp >= N_NODES) return;

    const int e0 = g_row_ptr[warp];
    const int e1 = g_row_ptr[warp + 1];

    float4 acc = make_float4(0.f, 0.f, 0.f, 0.f);
    const int fo = lane * 4;

    int e = e0;
    for (; e + 3 < e1; e += 4) {
        int   cc[4];
        float ww[4];
        #pragma unroll
        for (int j = 0; j < 4; ++j) { cc[j] = __ldg(&cols[e + j]); ww[j] = __ldg(&ew[e + j]); }
        #pragma unroll
        for (int j = 0; j < 4; ++j) {
            const float4 v = *(const float4*)&g_x[(size_t)cc[j] * OUT_FEAT + fo];
            acc.x = fmaf(ww[j], v.x, acc.x); acc.y = fmaf(ww[j], v.y, acc.y);
            acc.z = fmaf(ww[j], v.z, acc.z); acc.w = fmaf(ww[j], v.w, acc.w);
        }
    }
    for (; e < e1; ++e) {
        const int   c0 = __ldg(&cols[e]);
        const float w0 = __ldg(&ew[e]);
        const float4 v0 = *(const float4*)&g_x[(size_t)c0 * OUT_FEAT + fo];
        acc.x = fmaf(w0, v0.x, acc.x); acc.y = fmaf(w0, v0.y, acc.y);
        acc.z = fmaf(w0, v0.z, acc.z); acc.w = fmaf(w0, v0.w, acc.w);
    }

    acc.x = multispike(acc.x);
    acc.y = multispike(acc.y);
    acc.z = multispike(acc.z);
    acc.w = multispike(acc.w);
    *(float4*)&out[(size_t)warp * OUT_FEAT + fo] = acc;
}

// ---------------------------------------------------------------------------
extern "C" void kernel_launch(void* const* d_in, const int* in_sizes, int n_in,
                              void* d_out, int out_size) {
    const float* feat   = (const float*)d_in[0];
    const float* weight = (const float*)d_in[1];
    const int*   rows   = (const int*)d_in[2];
    const int*   cols   = (const int*)d_in[3];
    const float* ew     = (const float*)d_in[4];
    float* out = (float*)d_out;

    row_ptr_kernel<<<(N_EDGES / 4 + 255) / 256, 256>>>(rows);
    bprep_kernel<<<(32 * 16 * 32 + 255) / 256, 256>>>(weight);
    gemm_mma_kernel<<<(N_NODES + BM - 1) / BM, 128>>>(feat);
    spmm_kernel<<<(N_NODES * 32 + 255) / 256, 256>>>(cols, ew, out);
}